// round 17
// baseline (speedup 1.0000x reference)
#include <cuda_runtime.h>
#include <cuda_fp16.h>
#include <cstdint>

#define BB 2
#define SS 2048
#define DD 1024
#define HH 16
#define HD 64
#define MM (BB*SS)     // 4096

// ---------------- device scratch (no allocation allowed) -------------------
__device__ __half g_ahi[MM*DD];
__device__ __half g_wthi[4][DD*DD];
__device__ __half g_qh[BB*HH*SS*HD];
__device__ __half g_kh[BB*HH*SS*HD];
__device__ __half g_vh[BB*HH*SS*HD];

// ---------------- prepass: fp32 -> fp16 convert -----------------------------
__global__ __launch_bounds__(256)
void split_kernel(const float4* __restrict__ X, __half* __restrict__ Hi, int n4)
{
    union U { __half b[4]; uint64_t u; };
    for (int i = blockIdx.x * blockDim.x + threadIdx.x; i < n4;
         i += gridDim.x * blockDim.x) {
        float4 f = X[i];
        U h;
        h.b[0] = __float2half(f.x);
        h.b[1] = __float2half(f.y);
        h.b[2] = __float2half(f.z);
        h.b[3] = __float2half(f.w);
        ((uint64_t*)Hi)[i] = h.u;
    }
}

// ---------------- prepass: 4x W[k][n] -> Wt[n][k] fp16 ----------------------
__global__ __launch_bounds__(256)
void transpose_convert_kernel(const float* __restrict__ W0, const float* __restrict__ W1,
                              const float* __restrict__ W2, const float* __restrict__ W3,
                              __half* __restrict__ Th)
{
    __shared__ float tile[32][33];
    const float* Ws[4] = {W0, W1, W2, W3};
    const float* W = Ws[blockIdx.z];
    __half* th = Th + (size_t)blockIdx.z * DD * DD;
    int tx = threadIdx.x, ty = threadIdx.y;
    int x = blockIdx.x * 32 + tx;
    #pragma unroll
    for (int i = 0; i < 4; ++i) {
        int y = blockIdx.y * 32 + ty + i * 8;
        tile[ty + i * 8][tx] = W[(size_t)y * DD + x];
    }
    __syncthreads();
    int xo = blockIdx.y * 32 + tx;
    #pragma unroll
    for (int i = 0; i < 4; ++i) {
        int yo = blockIdx.x * 32 + ty + i * 8;
        th[(size_t)yo * DD + xo] = __float2half(tile[tx][ty + i * 8]);
    }
}

// ---------------- mma.sync / cp.async helpers --------------------------------
__device__ __forceinline__ uint32_t smem_u32(const void* p) {
    uint32_t a;
    asm("{ .reg .u64 t; cvta.to.shared.u64 t, %1; cvt.u32.u64 %0, t; }"
        : "=r"(a) : "l"(p));
    return a;
}
__device__ __forceinline__ void ldmx4(uint32_t* r, uint32_t addr) {
    asm volatile("ldmatrix.sync.aligned.m8n8.x4.shared.b16 {%0,%1,%2,%3}, [%4];"
                 : "=r"(r[0]), "=r"(r[1]), "=r"(r[2]), "=r"(r[3]) : "r"(addr));
}
__device__ __forceinline__ void ldmx4t(uint32_t* r, uint32_t addr) {
    asm volatile("ldmatrix.sync.aligned.m8n8.x4.trans.shared.b16 {%0,%1,%2,%3}, [%4];"
                 : "=r"(r[0]), "=r"(r[1]), "=r"(r[2]), "=r"(r[3]) : "r"(addr));
}
__device__ __forceinline__ void mma_f16(float* c, const uint32_t* a,
                                        uint32_t b0, uint32_t b1) {
    asm volatile(
        "mma.sync.aligned.m16n8k16.row.col.f32.f16.f16.f32 "
        "{%0,%1,%2,%3}, {%4,%5,%6,%7}, {%8,%9}, {%0,%1,%2,%3};"
        : "+f"(c[0]), "+f"(c[1]), "+f"(c[2]), "+f"(c[3])
        : "r"(a[0]), "r"(a[1]), "r"(a[2]), "r"(a[3]), "r"(b0), "r"(b1));
}
__device__ __forceinline__ float ex2f(float x) {
    float y; asm("ex2.approx.f32 %0, %1;" : "=f"(y) : "f"(x)); return y;
}
__device__ __forceinline__ uint32_t pack_f16x2(float a, float b) {
    __half2 t = __floats2half2_rn(a, b);
    return *(uint32_t*)&t;
}
__device__ __forceinline__ void cpa16(uint32_t dst, const void* src) {
    asm volatile("cp.async.cg.shared.global [%0], [%1], 16;" :: "r"(dst), "l"(src));
}
__device__ __forceinline__ void cpa_commit() {
    asm volatile("cp.async.commit_group;" ::: "memory");
}
template<int N> __device__ __forceinline__ void cpa_wait() {
    asm volatile("cp.async.wait_group %0;" :: "n"(N) : "memory");
}

// ---------------- HMMA GEMM core (swizzled 64B rows, 3-stage, 1-pass) --------
#define GCH 32
#define GOP 8192                     // 128 rows * 64 B
#define GSTG (2*GOP)                 // 16384 B per stage (A | B)
#define GEMM_SMEM (3*GSTG)           // 49152 B

__device__ __forceinline__ uint32_t sw64(uint32_t off) {
    return off ^ (((off >> 7) & 3u) << 4);
}

template<typename EPI>
__device__ __forceinline__ void gemm_core(
    const __half* Ahi, const __half* Bhi, int m0, int n0, EPI epi)
{
    extern __shared__ __align__(16) char gsm[];
    const uint32_t base = smem_u32(gsm);

    const int tid  = threadIdx.x;
    const int wid  = tid >> 5;
    const int lane = tid & 31;
    const int wm0 = (wid & 3) * 32;
    const int wn0 = (wid >> 2) * 64;

    const uint4* srcs[2] = {(const uint4*)Ahi, (const uint4*)Bhi};

    // copy mapping: 1024 uint4 per chunk, 4 per thread
    int cmat[4], crow[4], cc4[4];
    uint32_t cdst[4];
    #pragma unroll
    for (int i = 0; i < 4; ++i) {
        int idx = tid + i * 256;
        cmat[i] = idx >> 9;
        int w = idx & 511;
        crow[i] = w >> 2;
        cc4[i]  = w & 3;
        cdst[i] = base + cmat[i]*GOP + sw64(crow[i]*64 + cc4[i]*16);
    }

    auto issue = [&](int t) {
        const uint32_t so = (t % 3) * GSTG;
        #pragma unroll
        for (int i = 0; i < 4; ++i) {
            const int r0 = (cmat[i] == 0) ? m0 : n0;
            cpa16(cdst[i] + so, srcs[cmat[i]] + (size_t)(r0 + crow[i])*128 + t*4 + cc4[i]);
        }
        cpa_commit();
    };

    uint32_t aoffb[2], axor[2], boffb[4], bxor[4];
    #pragma unroll
    for (int mf = 0; mf < 2; ++mf) {
        int row = wm0 + mf*16 + (lane & 15);
        aoffb[mf] = row*64 + (lane >> 4)*16;
        axor[mf]  = ((row >> 1) & 3u) << 4;
    }
    #pragma unroll
    for (int np = 0; np < 4; ++np) {
        int row = wn0 + np*16 + ((lane >> 4) & 1)*8 + (lane & 7);
        boffb[np] = row*64 + ((lane >> 3) & 1)*16;
        bxor[np]  = ((row >> 1) & 3u) << 4;
    }

    float acc[2][8][4] = {};

    auto compute = [&](int stg) {
        const uint32_t sb = base + stg * GSTG;
        #pragma unroll
        for (int ks2 = 0; ks2 < 64; ks2 += 32) {
            uint32_t afh[2][4], bfh[4][4];
            #pragma unroll
            for (int mf = 0; mf < 2; ++mf) {
                uint32_t o = (aoffb[mf] + ks2) ^ axor[mf];
                ldmx4(afh[mf], sb + o);
            }
            #pragma unroll
            for (int np = 0; np < 4; ++np) {
                uint32_t o = (boffb[np] + ks2) ^ bxor[np];
                ldmx4(bfh[np], sb + GOP + o);
            }
            #pragma unroll
            for (int mf = 0; mf < 2; ++mf)
                #pragma unroll
                for (int np = 0; np < 4; ++np) {
                    mma_f16(acc[mf][np*2+0], afh[mf], bfh[np][0], bfh[np][1]);
                    mma_f16(acc[mf][np*2+1], afh[mf], bfh[np][2], bfh[np][3]);
                }
        }
    };

    issue(0); issue(1);
    for (int t = 0; t < GCH; ++t) {
        if (t + 1 < GCH) cpa_wait<1>(); else cpa_wait<0>();
        __syncthreads();
        if (t + 2 < GCH) issue(t + 2);
        compute(t % 3);
    }

    const int qrow = lane >> 2;
    const int qcol = (lane & 3) * 2;
    #pragma unroll
    for (int mf = 0; mf < 2; ++mf)
        #pragma unroll
        for (int nf = 0; nf < 8; ++nf)
            #pragma unroll
            for (int half = 0; half < 2; ++half) {
                const int m = m0 + wm0 + mf*16 + qrow + half*8;
                const int n = n0 + wn0 + nf*8 + qcol;
                epi(m, n, acc[mf][nf][half*2 + 0], acc[mf][nf][half*2 + 1]);
            }
}

// fused QKV projection (1-pass fp16)
__global__ __launch_bounds__(256, 2)
void mma_gemm_qkv(const __half* __restrict__ Ahi, const __half* __restrict__ Whi,
                  __half* __restrict__ qh, __half* __restrict__ kh,
                  __half* __restrict__ vh)
{
    const int g  = blockIdx.x >> 3;
    const int n0 = (blockIdx.x & 7) * 128;
    const int m0 = blockIdx.y * 128;
    const __half* Bhi = Whi + (size_t)g * DD * DD;
    __half* Yh = (g == 0) ? qh : (g == 1) ? kh : vh;

    gemm_core(Ahi, Bhi, m0, n0,
        [&](int m, int n, float cx, float cy) {
            const int b = m >> 11, s = m & (SS - 1);
            const int h = n >> 6, hd = n & 63;
            const size_t off = (((size_t)b*HH + h)*SS + s)*HD + hd;
            *(uint32_t*)(Yh + off) = pack_f16x2(cx, cy);
        });
}

// output projection + bias (1-pass fp16)
__global__ __launch_bounds__(256, 2)
void mma_gemm_out(const __half* __restrict__ Ahi, const __half* __restrict__ Bhi,
                  float* __restrict__ Yf, const float* __restrict__ bias)
{
    const int n0 = blockIdx.x * 128;
    const int m0 = blockIdx.y * 128;
    gemm_core(Ahi, Bhi, m0, n0,
        [&](int m, int n, float cx, float cy) {
            float2* dst = (float2*)(Yf + (size_t)m * DD + n);
            *dst = make_float2(cx + bias[n], cy + bias[n + 1]);
        });
}

// ---------------- HMMA flash attention (fp16, online softmax) ----------------
#define KST 72
#define STAGE (2*64*KST*2)           // 18432 B (Kh | Vh)
#define ATTN_SMEM (2*STAGE)          // 36864 B
#define LOG2E 1.4426950408889634f

__global__ __launch_bounds__(256, 2)
void attn_mma(const __half* __restrict__ Qh,
              const __half* __restrict__ Kh, const __half* __restrict__ Vh,
              __half* __restrict__ Chi)
{
    extern __shared__ __align__(16) char dynsm[];
    __half* sm = (__half*)dynsm;

    const int bh  = blockIdx.y;
    const int tid = threadIdx.x;
    const int wid = tid >> 5;
    const int lane = tid & 31;
    const int wrow0 = wid * 16;

    const size_t hbase = (size_t)bh * SS * HD;
    const uint4* Kh4 = (const uint4*)(Kh + hbase);
    const uint4* Vh4 = (const uint4*)(Vh + hbase);

    const uint32_t sbase = smem_u32(sm);

    uint32_t kbase[4];
    #pragma unroll
    for (int ng = 0; ng < 4; ++ng) {
        int krow = ng*16 + ((lane >> 4) & 1)*8 + (lane & 7);
        kbase[ng] = (krow * KST + ((lane >> 3) & 1) * 8) * 2;
    }
    const uint32_t vrowoff = ((((lane >> 3) & 1)*8 + (lane & 7)) * KST) * 2;
    uint32_t vcol[4];
    #pragma unroll
    for (int ng = 0; ng < 4; ++ng)
        vcol[ng] = (ng*16 + (lane >> 4) * 8) * 2;

    uint32_t cpa_dst[4];
    int cpa_src[4];
    #pragma unroll
    for (int i = 0; i < 4; ++i) {
        int idx = tid + i * 256;
        int tile = idx >> 9;
        int within = idx & 511;
        int row = within >> 3, c = within & 7;
        cpa_dst[i] = sbase + ((tile*64 + row)*KST + c*8) * 2;
        cpa_src[i] = within;
    }

    auto issue = [&](int kt) {
        const uint4* srcs[2] = {Kh4 + kt*512, Vh4 + kt*512};
        const uint32_t soff = (kt & 1) * STAGE;
        #pragma unroll
        for (int i = 0; i < 4; ++i) {
            int tile = (tid + i*256) >> 9;
            cpa16(cpa_dst[i] + soff, srcs[tile] + cpa_src[i]);
        }
        cpa_commit();
    };

    #pragma unroll 1
    for (int half = 0; half < 2; ++half) {
        const int qi = half ? (15 - blockIdx.x) : blockIdx.x;

        __syncthreads();
        {
            const uint4* Qh4 = (const uint4*)(Qh + hbase + (size_t)qi*128*HD);
            #pragma unroll
            for (int i = 0; i < 4; ++i) {
                int idx = tid + i * 256;
                int row = idx >> 3, c = idx & 7;
                uint4 v = Qh4[idx];
                *(uint4*)&sm[row*KST + c*8] = v;
            }
        }
        __syncthreads();

        uint32_t qhf[4][4];
        {
            const uint32_t roff = ((wrow0 + (lane & 15)) * KST + (lane >> 4) * 8) * 2;
            #pragma unroll
            for (int ks = 0; ks < 4; ++ks)
                ldmx4(qhf[ks], sbase + roff + ks * 32);
        }
        __syncthreads();

        float mrow[2] = {-1e30f, -1e30f};
        float lrow[2] = {0.0f, 0.0f};
        float o[8][4] = {};

        const int wmax = qi*128 + wrow0 + 15;
        const int nsteps = 2*qi + 2;

        issue(0);
        for (int kt = 0; kt < nsteps; ++kt) {
            if (kt + 1 < nsteps) { issue(kt + 1); cpa_wait<1>(); }
            else                 { cpa_wait<0>(); }
            __syncthreads();

            const uint32_t st = sbase + (kt & 1) * STAGE;
            const uint32_t sKh = st;
            const uint32_t sVh = st + 64*KST*2;

            if (kt*64 <= wmax) {
                float s[8][4] = {};
                #pragma unroll
                for (int ks = 0; ks < 4; ++ks) {
                    #pragma unroll
                    for (int ng = 0; ng < 4; ++ng) {
                        uint32_t khb[4];
                        ldmx4(khb, sKh + kbase[ng] + ks*32);
                        mma_f16(s[2*ng+0], qhf[ks], khb[0], khb[1]);
                        mma_f16(s[2*ng+1], qhf[ks], khb[2], khb[3]);
                    }
                }

                const float SC = 0.125f * LOG2E;
                const int r0g = qi*128 + wrow0 + (lane >> 2);
                const bool needmask = (kt*64 + 63 > qi*128 + wrow0);
                #pragma unroll
                for (int nf = 0; nf < 8; ++nf)
                    #pragma unroll
                    for (int ri = 0; ri < 4; ++ri) {
                        float v = s[nf][ri] * SC;
                        if (needmask) {
                            int col = kt*64 + nf*8 + (lane & 3)*2 + (ri & 1);
                            int rg  = r0g + ((ri >> 1) ? 8 : 0);
                            if (col > rg) v = -1e30f;
                        }
                        s[nf][ri] = v;
                    }

                float alpha[2];
                #pragma unroll
                for (int h = 0; h < 2; ++h) {
                    float t = -1e30f;
                    #pragma unroll
                    for (int nf = 0; nf < 8; ++nf)
                        t = fmaxf(t, fmaxf(s[nf][h*2], s[nf][h*2+1]));
                    t = fmaxf(t, __shfl_xor_sync(0xffffffffu, t, 1));
                    t = fmaxf(t, __shfl_xor_sync(0xffffffffu, t, 2));
                    float nm = fmaxf(mrow[h], t);
                    alpha[h] = ex2f(mrow[h] - nm);
                    mrow[h] = nm;
                }
                float rs[2] = {0.0f, 0.0f};
                #pragma unroll
                for (int nf = 0; nf < 8; ++nf)
                    #pragma unroll
                    for (int ri = 0; ri < 4; ++ri) {
                        int h = ri >> 1;
                        float p = ex2f(s[nf][ri] - mrow[h]);
                        s[nf][ri] = p;
                        rs[h] += p;
                    }
                #pragma unroll
                for (int h = 0; h < 2; ++h) {
                    rs[h] += __shfl_xor_sync(0xffffffffu, rs[h], 1);
                    rs[h] += __shfl_xor_sync(0xffffffffu, rs[h], 2);
                    lrow[h] = lrow[h] * alpha[h] + rs[h];
                }
                #pragma unroll
                for (int nf = 0; nf < 8; ++nf) {
                    o[nf][0] *= alpha[0]; o[nf][1] *= alpha[0];
                    o[nf][2] *= alpha[1]; o[nf][3] *= alpha[1];
                }

                uint32_t pah[4][4];
                #pragma unroll
                for (int ks = 0; ks < 4; ++ks) {
                    pah[ks][0] = pack_f16x2(s[2*ks][0],   s[2*ks][1]);
                    pah[ks][1] = pack_f16x2(s[2*ks][2],   s[2*ks][3]);
                    pah[ks][2] = pack_f16x2(s[2*ks+1][0], s[2*ks+1][1]);
                    pah[ks][3] = pack_f16x2(s[2*ks+1][2], s[2*ks+1][3]);
                }

                #pragma unroll
                for (int ks = 0; ks < 4; ++ks) {
                    const uint32_t vrb = vrowoff + ks*16*KST*2;
                    #pragma unroll
                    for (int ng = 0; ng < 4; ++ng) {
                        uint32_t vhb[4];
                        ldmx4t(vhb, sVh + vrb + vcol[ng]);
                        mma_f16(o[2*ng+0], pah[ks], vhb[0], vhb[1]);
                        mma_f16(o[2*ng+1], pah[ks], vhb[2], vhb[3]);
                    }
                }
            }
            __syncthreads();
        }

        const float inv0 = 1.0f / lrow[0];
        const float inv1 = 1.0f / lrow[1];
        const int b = bh >> 4, h = bh & 15;
        const int r0 = qi*128 + wrow0 + (lane >> 2);
        #pragma unroll
        for (int nf = 0; nf < 8; ++nf) {
            const int col = h*HD + nf*8 + (lane & 3)*2;
            const size_t off0 = ((size_t)b*SS + r0)*DD + col;
            const size_t off1 = ((size_t)b*SS + r0 + 8)*DD + col;
            *(uint32_t*)(Chi + off0) = pack_f16x2(o[nf][0]*inv0, o[nf][1]*inv0);
            *(uint32_t*)(Chi + off1) = pack_f16x2(o[nf][2]*inv1, o[nf][3]*inv1);
        }
    }
}

// ---------------------------------------------------------------------------

extern "C" void kernel_launch(void* const* d_in, const int* in_sizes, int n_in,
                              void* d_out, int out_size)
{
    const float* x  = (const float*)d_in[0];
    const float* Wq = (const float*)d_in[1];
    const float* Wk = (const float*)d_in[2];
    const float* Wv = (const float*)d_in[3];
    const float* Wo = (const float*)d_in[4];
    const float* bo = (const float*)d_in[5];
    float* out = (float*)d_out;

    __half *ahi, *wthi, *qh, *kh, *vh;
    cudaGetSymbolAddress((void**)&ahi,  g_ahi);
    cudaGetSymbolAddress((void**)&wthi, g_wthi);
    cudaGetSymbolAddress((void**)&qh,   g_qh);
    cudaGetSymbolAddress((void**)&kh,   g_kh);
    cudaGetSymbolAddress((void**)&vh,   g_vh);

    cudaFuncSetAttribute(attn_mma, cudaFuncAttributeMaxDynamicSharedMemorySize, ATTN_SMEM);
    cudaFuncSetAttribute(mma_gemm_qkv, cudaFuncAttributeMaxDynamicSharedMemorySize, GEMM_SMEM);
    cudaFuncSetAttribute(mma_gemm_out, cudaFuncAttributeMaxDynamicSharedMemorySize, GEMM_SMEM);

    // 1. convert X to fp16
    split_kernel<<<1024, 256>>>((const float4*)x, ahi, MM*DD/4);

    // 2. transpose+convert all 4 weights (one launch)
    transpose_convert_kernel<<<dim3(32,32,4), dim3(32,8)>>>(Wq, Wk, Wv, Wo, wthi);

    // 3. fused Q/K/V projections (fp16 1-pass)
    mma_gemm_qkv<<<dim3(24, 32), 256, GEMM_SMEM>>>(ahi, wthi, qh, kh, vh);

    // 4. attention (fp16, online softmax, balanced pairs)
    attn_mma<<<dim3(8, BB*HH), 256, ATTN_SMEM>>>(qh, kh, vh, ahi);

    // 5. output projection + bias (fp16 1-pass)
    mma_gemm_out<<<dim3(8, 32), 256, GEMM_SMEM>>>(ahi, wthi + 3*(size_t)DD*DD, out, bo);
}